// round 15
// baseline (speedup 1.0000x reference)
#include <cuda_runtime.h>
#include <math.h>

namespace {
constexpr int B = 4;
constexpr int N = 10000;
constexpr int E = 160000;
constexpr int HIST = 8;
constexpr int PRED = 12;
constexpr int HID = 64;
constexpr int GNN_OUT = 13;
constexpr int IN_DIM = 9;
constexpr int BN = B * N;
constexpr int TSTEPS = HIST + PRED; // 20
}

// Persistent scratch (device globals — no allocation allowed)
__device__ float g_x[BN * IN_DIM];        // node features [B*N][9]
__device__ float g_hn[HID * BN];          // GRU state, transposed [64][B*N] for coalescing
__device__ float g_agg[BN * GNN_OUT];     // scatter target [B*N][13]
__device__ float g_stats[8];              // sum0,sum1,sq0,sq1, mean0,mean1,istd0,istd1
__device__ int   g_is64;                  // edge_index dtype flag

__device__ __forceinline__ float sigmoidf_(float x) {
    return 1.0f / (1.0f + __expf(-x));
}

// ---------------------------------------------------------------------------
// Detect int64 vs int32 edge_index (values < 10000 => high 32-bit words all 0
// iff int64), and zero the stats accumulators.
// ---------------------------------------------------------------------------
__global__ void k_detect(const unsigned int* __restrict__ ei_raw) {
    __shared__ int s_ok;
    if (threadIdx.x == 0) s_ok = 1;
    __syncthreads();
    if (ei_raw[2 * threadIdx.x + 1] != 0u) s_ok = 0;  // benign same-value race
    __syncthreads();
    if (threadIdx.x < 4) g_stats[threadIdx.x] = 0.0f;
    if (threadIdx.x == 0) g_is64 = s_ok;
}

// ---------------------------------------------------------------------------
// edge_attr mean / sample-std (ddof=1) over E rows, 2 cols
// ---------------------------------------------------------------------------
__global__ void k_stats(const float* __restrict__ ea) {
    float s0 = 0.f, s1 = 0.f, q0 = 0.f, q1 = 0.f;
    for (int e = blockIdx.x * blockDim.x + threadIdx.x; e < E;
         e += gridDim.x * blockDim.x) {
        float a0 = ea[2 * e], a1 = ea[2 * e + 1];
        s0 += a0; s1 += a1; q0 += a0 * a0; q1 += a1 * a1;
    }
#pragma unroll
    for (int o = 16; o > 0; o >>= 1) {
        s0 += __shfl_down_sync(0xffffffffu, s0, o);
        s1 += __shfl_down_sync(0xffffffffu, s1, o);
        q0 += __shfl_down_sync(0xffffffffu, q0, o);
        q1 += __shfl_down_sync(0xffffffffu, q1, o);
    }
    __shared__ float sh[4][8];
    int w = threadIdx.x >> 5, l = threadIdx.x & 31;
    if (l == 0) { sh[0][w] = s0; sh[1][w] = s1; sh[2][w] = q0; sh[3][w] = q1; }
    __syncthreads();
    if (threadIdx.x == 0) {
        float t0 = 0.f, t1 = 0.f, t2 = 0.f, t3 = 0.f;
        int nwp = blockDim.x >> 5;
        for (int k = 0; k < nwp; k++) {
            t0 += sh[0][k]; t1 += sh[1][k]; t2 += sh[2][k]; t3 += sh[3][k];
        }
        atomicAdd(&g_stats[0], t0); atomicAdd(&g_stats[1], t1);
        atomicAdd(&g_stats[2], t2); atomicAdd(&g_stats[3], t3);
    }
}

__global__ void k_finalize() {
    float inv = 1.0f / (float)E;
    float m0 = g_stats[0] * inv, m1 = g_stats[1] * inv;
    float v0 = (g_stats[2] - g_stats[0] * m0) / (float)(E - 1);
    float v1 = (g_stats[3] - g_stats[1] * m1) / (float)(E - 1);
    float sd0 = fmaxf(sqrtf(fmaxf(v0, 0.f)), 1e-6f);
    float sd1 = fmaxf(sqrtf(fmaxf(v1, 0.f)), 1e-6f);
    g_stats[4] = m0; g_stats[5] = m1;
    g_stats[6] = 1.0f / sd0; g_stats[7] = 1.0f / sd1;
}

// ---------------------------------------------------------------------------
// Init: x0 = [pm25_hist[:, -1], feature[:, HIST]]; hn = 0; agg = 0
// ---------------------------------------------------------------------------
__global__ void k_init(const float* __restrict__ pm25,
                       const float* __restrict__ feat) {
    int i = blockIdx.x * 256 + threadIdx.x;
    if (i >= BN) return;
    int b = i / N, n = i % N;
    float* x = g_x + (size_t)i * IN_DIM;
    x[0] = pm25[(size_t)(b * HIST + (HIST - 1)) * N + n];
    const float* f = feat + ((size_t)(b * TSTEPS + HIST) * N + n) * 8;
#pragma unroll
    for (int k = 0; k < 8; k++) x[1 + k] = f[k];
#pragma unroll
    for (int j = 0; j < HID; j++) g_hn[j * BN + i] = 0.0f;
#pragma unroll
    for (int k = 0; k < GNN_OUT; k++) g_agg[(size_t)i * GNN_OUT + k] = 0.0f;
}

// ---------------------------------------------------------------------------
// Edge kernel: one thread per (batch, edge).
// Computes edge MLP (21->32->30, sigmoid), folds in the node projection
// (30->13) so only 13 values get scattered (+tgt / -src) per edge.
// ---------------------------------------------------------------------------
__global__ void __launch_bounds__(256) k_edge(
    const float* __restrict__ ea, const void* __restrict__ ei,
    const float* __restrict__ wm, const float* __restrict__ ws,
    const float* __restrict__ ew1, const float* __restrict__ eb1,
    const float* __restrict__ ew2, const float* __restrict__ eb2,
    const float* __restrict__ nw)
{
    __shared__ float s_w1[21 * 32];
    __shared__ float s_b1[32];
    __shared__ float s_w2[32 * 30];
    __shared__ float s_b2[30];
    __shared__ float s_nw[30 * 13];
    for (int i = threadIdx.x; i < 21 * 32; i += 256) s_w1[i] = ew1[i];
    for (int i = threadIdx.x; i < 32; i += 256) s_b1[i] = eb1[i];
    for (int i = threadIdx.x; i < 32 * 30; i += 256) s_w2[i] = ew2[i];
    for (int i = threadIdx.x; i < 30; i += 256) s_b2[i] = eb2[i];
    for (int i = threadIdx.x; i < 30 * 13; i += 256) s_nw[i] = nw[i];
    __syncthreads();

    int idx = blockIdx.x * 256 + threadIdx.x;
    if (idx >= B * E) return;
    int e = idx % E;
    int b = idx / E;

    int src, tgt;
    if (g_is64) {
        const long long* p = (const long long*)ei;
        src = (int)p[e]; tgt = (int)p[E + e];
    } else {
        const int* p = (const int*)ei;
        src = p[e]; tgt = p[E + e];
    }

    const float* xs = g_x + (size_t)(b * N + src) * IN_DIM;
    const float* xt = g_x + (size_t)(b * N + tgt) * IN_DIM;
    float in[21];
#pragma unroll
    for (int k = 0; k < 9; k++) in[k] = xs[k];
#pragma unroll
    for (int k = 0; k < 9; k++) in[9 + k] = xt[k];

    float a0 = ea[2 * e], a1 = ea[2 * e + 1];
    in[18] = (a0 - g_stats[4]) * g_stats[6];
    in[19] = (a1 - g_stats[5]) * g_stats[7];
    float dist = fmaxf(a0, 1e-3f);
    float wsd0 = fmaxf(ws[0], 1e-6f);
    float wsd1 = fmaxf(ws[1], 1e-6f);
    float wind0 = in[7] * wsd0 + wm[0];   // src last-2 features are x[7], x[8]
    float wind1 = in[8] * wsd1 + wm[1];
    float speed = fmaxf(wind0, 0.0f);
    float wdir = wind1 * 0.017453292519943295f;  // deg2rad
    float theta = fabsf(a1 - wdir);
    in[20] = fmaxf(0.0f, 3.0f * speed * cosf(theta) / dist);

    float h1[32];
#pragma unroll
    for (int j = 0; j < 32; j++) {
        float acc = s_b1[j];
#pragma unroll
        for (int i = 0; i < 21; i++) acc += in[i] * s_w1[i * 32 + j];
        h1[j] = sigmoidf_(acc);
    }
    float h2[30];
#pragma unroll
    for (int j = 0; j < 30; j++) {
        float acc = s_b2[j];
#pragma unroll
        for (int i = 0; i < 32; i++) acc += h1[i] * s_w2[i * 30 + j];
        h2[j] = sigmoidf_(acc);
    }

    float* at = g_agg + (size_t)(b * N + tgt) * GNN_OUT;
    float* as = g_agg + (size_t)(b * N + src) * GNN_OUT;
#pragma unroll
    for (int k = 0; k < GNN_OUT; k++) {
        float v = 0.0f;
#pragma unroll
        for (int j = 0; j < 30; j++) v += h2[j] * s_nw[j * 13 + k];
        atomicAdd(at + k, v);
        atomicAdd(as + k, -v);
    }
}

// ---------------------------------------------------------------------------
// Node kernel: x_gnn = sigmoid(agg + n_b); xc = [x_gnn, x]; GRU; fc;
// writes output for step t, zeroes agg, and builds x for step t+1.
// Weights staged in 68KB dynamic shared.
// ---------------------------------------------------------------------------
__global__ void __launch_bounds__(128) k_node(
    const float* __restrict__ feat,
    const float* __restrict__ gwi, const float* __restrict__ gwh,
    const float* __restrict__ gbi, const float* __restrict__ gbh,
    const float* __restrict__ nb, const float* __restrict__ fcw,
    const float* __restrict__ fcb, float* __restrict__ out, int t)
{
    extern __shared__ float sm[];
    float* s_wi = sm;                 // 192*22 = 4224
    float* s_wh = sm + 4224;          // 192*64 = 12288 (16B aligned)
    float* s_bi = s_wh + 12288;       // 192
    float* s_bh = s_bi + 192;         // 192
    float* s_nb = s_bh + 192;         // 13
    float* s_fw = s_nb + 13;          // 64
    for (int i = threadIdx.x; i < 4224; i += 128) s_wi[i] = gwi[i];
    for (int i = threadIdx.x; i < 12288; i += 128) s_wh[i] = gwh[i];
    for (int i = threadIdx.x; i < 192; i += 128) { s_bi[i] = gbi[i]; s_bh[i] = gbh[i]; }
    for (int i = threadIdx.x; i < 64; i += 128) s_fw[i] = fcw[i];
    if (threadIdx.x < 13) s_nb[threadIdx.x] = nb[threadIdx.x];
    __syncthreads();

    int i = blockIdx.x * 128 + threadIdx.x;
    if (i >= BN) return;
    int b = i / N, n = i % N;

    float xc[22];
    float* agg = g_agg + (size_t)i * GNN_OUT;
#pragma unroll
    for (int k = 0; k < 13; k++) {
        xc[k] = sigmoidf_(agg[k] + s_nb[k]);
        agg[k] = 0.0f;  // zero for next step's scatter
    }
    const float* xrow = g_x + (size_t)i * IN_DIM;
#pragma unroll
    for (int k = 0; k < 9; k++) xc[13 + k] = xrow[k];

    float h[64];
#pragma unroll
    for (int j = 0; j < 64; j++) h[j] = g_hn[j * BN + i];

    float xn = fcb[0];
    for (int k = 0; k < 64; k++) {
        float ir = s_bi[k], iz = s_bi[64 + k], inn = s_bi[128 + k];
        const float* wr = s_wi + k * 22;
        const float* wz = s_wi + (64 + k) * 22;
        const float* wn = s_wi + (128 + k) * 22;
#pragma unroll
        for (int q = 0; q < 22; q++) {
            float xq = xc[q];
            ir += xq * wr[q]; iz += xq * wz[q]; inn += xq * wn[q];
        }
        float hr = s_bh[k], hz = s_bh[64 + k], hnn = s_bh[128 + k];
        const float4* vr = (const float4*)(s_wh + k * 64);
        const float4* vz = (const float4*)(s_wh + (64 + k) * 64);
        const float4* vn = (const float4*)(s_wh + (128 + k) * 64);
#pragma unroll
        for (int q = 0; q < 16; q++) {
            float4 a = vr[q], c = vz[q], d = vn[q];
            hr  += h[4 * q] * a.x + h[4 * q + 1] * a.y + h[4 * q + 2] * a.z + h[4 * q + 3] * a.w;
            hz  += h[4 * q] * c.x + h[4 * q + 1] * c.y + h[4 * q + 2] * c.z + h[4 * q + 3] * c.w;
            hnn += h[4 * q] * d.x + h[4 * q + 1] * d.y + h[4 * q + 2] * d.z + h[4 * q + 3] * d.w;
        }
        float r = sigmoidf_(ir + hr);
        float z = sigmoidf_(iz + hz);
        float ng = tanhf(inn + r * hnn);
        float h_old = g_hn[k * BN + i];       // read-before-write, same thread
        float hk = (1.0f - z) * ng + z * h_old;
        g_hn[k * BN + i] = hk;
        xn += hk * s_fw[k];
    }

    out[(size_t)(b * N + n) * PRED + t] = xn;

    if (t + 1 < PRED) {
        float* xw = g_x + (size_t)i * IN_DIM;
        xw[0] = xn;
        const float* f = feat + ((size_t)(b * TSTEPS + HIST + t + 1) * N + n) * 8;
#pragma unroll
        for (int k = 0; k < 8; k++) xw[1 + k] = f[k];
    }
}

// ---------------------------------------------------------------------------
extern "C" void kernel_launch(void* const* d_in, const int* in_sizes, int n_in,
                              void* d_out, int out_size) {
    const float* pm25 = (const float*)d_in[0];
    const float* feat = (const float*)d_in[1];
    const float* ea   = (const float*)d_in[2];
    const float* wm   = (const float*)d_in[3];
    const float* ws   = (const float*)d_in[4];
    const float* ew1  = (const float*)d_in[5];
    const float* eb1  = (const float*)d_in[6];
    const float* ew2  = (const float*)d_in[7];
    const float* eb2  = (const float*)d_in[8];
    const float* nw   = (const float*)d_in[9];
    const float* nb   = (const float*)d_in[10];
    const float* gwi  = (const float*)d_in[11];
    const float* gwh  = (const float*)d_in[12];
    const float* gbi  = (const float*)d_in[13];
    const float* gbh  = (const float*)d_in[14];
    const float* fcw  = (const float*)d_in[15];
    const float* fcb  = (const float*)d_in[16];
    const void*  ei   = d_in[17];
    float* out = (float*)d_out;

    constexpr int NODE_SMEM = (4224 + 12288 + 192 + 192 + 13 + 64) * 4; // 67892 B
    cudaFuncSetAttribute(k_node, cudaFuncAttributeMaxDynamicSharedMemorySize,
                         NODE_SMEM);

    k_detect<<<1, 256>>>((const unsigned int*)ei);
    k_stats<<<232, 256>>>(ea);
    k_finalize<<<1, 1>>>();
    k_init<<<(BN + 255) / 256, 256>>>(pm25, feat);

    for (int t = 0; t < PRED; t++) {
        k_edge<<<(B * E + 255) / 256, 256>>>(ea, ei, wm, ws, ew1, eb1, ew2,
                                             eb2, nw);
        k_node<<<(BN + 127) / 128, 128, NODE_SMEM>>>(feat, gwi, gwh, gbi, gbh,
                                                     nb, fcw, fcb, out, t);
    }
}

// round 16
// speedup vs baseline: 1.0050x; 1.0050x over previous
#include <cuda_runtime.h>
#include <math.h>

namespace {
constexpr int B = 4;
constexpr int N = 10000;
constexpr int E = 160000;
constexpr int HIST = 8;
constexpr int PRED = 12;
constexpr int HID = 64;
constexpr int GNN_OUT = 13;
constexpr int IN_DIM = 9;
constexpr int BN = B * N;
constexpr int TSTEPS = HIST + PRED; // 20
}

// Persistent scratch (device globals — no allocation allowed)
__device__ float g_x[BN * IN_DIM];        // node features [B*N][9]
__device__ float g_hn[HID * BN];          // GRU state, transposed [64][B*N] for coalescing
__device__ float g_agg[BN * GNN_OUT];     // scatter target [B*N][13]
__device__ float g_stats[8];              // sum0,sum1,sq0,sq1, mean0,mean1,istd0,istd1
__device__ int   g_is64;                  // edge_index dtype flag

__device__ __forceinline__ float sigmoidf_(float x) {
    return 1.0f / (1.0f + __expf(-x));
}

// ---------------------------------------------------------------------------
// Detect int64 vs int32 edge_index (values < 10000 => high 32-bit words all 0
// iff int64), and zero the stats accumulators.
// ---------------------------------------------------------------------------
__global__ void k_detect(const unsigned int* __restrict__ ei_raw) {
    __shared__ int s_ok;
    if (threadIdx.x == 0) s_ok = 1;
    __syncthreads();
    if (ei_raw[2 * threadIdx.x + 1] != 0u) s_ok = 0;  // benign same-value race
    __syncthreads();
    if (threadIdx.x < 4) g_stats[threadIdx.x] = 0.0f;
    if (threadIdx.x == 0) g_is64 = s_ok;
}

// ---------------------------------------------------------------------------
// edge_attr mean / sample-std (ddof=1) over E rows, 2 cols
// ---------------------------------------------------------------------------
__global__ void k_stats(const float* __restrict__ ea) {
    float s0 = 0.f, s1 = 0.f, q0 = 0.f, q1 = 0.f;
    for (int e = blockIdx.x * blockDim.x + threadIdx.x; e < E;
         e += gridDim.x * blockDim.x) {
        float a0 = ea[2 * e], a1 = ea[2 * e + 1];
        s0 += a0; s1 += a1; q0 += a0 * a0; q1 += a1 * a1;
    }
#pragma unroll
    for (int o = 16; o > 0; o >>= 1) {
        s0 += __shfl_down_sync(0xffffffffu, s0, o);
        s1 += __shfl_down_sync(0xffffffffu, s1, o);
        q0 += __shfl_down_sync(0xffffffffu, q0, o);
        q1 += __shfl_down_sync(0xffffffffu, q1, o);
    }
    __shared__ float sh[4][8];
    int w = threadIdx.x >> 5, l = threadIdx.x & 31;
    if (l == 0) { sh[0][w] = s0; sh[1][w] = s1; sh[2][w] = q0; sh[3][w] = q1; }
    __syncthreads();
    if (threadIdx.x == 0) {
        float t0 = 0.f, t1 = 0.f, t2 = 0.f, t3 = 0.f;
        int nwp = blockDim.x >> 5;
        for (int k = 0; k < nwp; k++) {
            t0 += sh[0][k]; t1 += sh[1][k]; t2 += sh[2][k]; t3 += sh[3][k];
        }
        atomicAdd(&g_stats[0], t0); atomicAdd(&g_stats[1], t1);
        atomicAdd(&g_stats[2], t2); atomicAdd(&g_stats[3], t3);
    }
}

__global__ void k_finalize() {
    float inv = 1.0f / (float)E;
    float m0 = g_stats[0] * inv, m1 = g_stats[1] * inv;
    float v0 = (g_stats[2] - g_stats[0] * m0) / (float)(E - 1);
    float v1 = (g_stats[3] - g_stats[1] * m1) / (float)(E - 1);
    float sd0 = fmaxf(sqrtf(fmaxf(v0, 0.f)), 1e-6f);
    float sd1 = fmaxf(sqrtf(fmaxf(v1, 0.f)), 1e-6f);
    g_stats[4] = m0; g_stats[5] = m1;
    g_stats[6] = 1.0f / sd0; g_stats[7] = 1.0f / sd1;
}

// ---------------------------------------------------------------------------
// Init: x0 = [pm25_hist[:, -1], feature[:, HIST]]; hn = 0; agg = 0
// ---------------------------------------------------------------------------
__global__ void k_init(const float* __restrict__ pm25,
                       const float* __restrict__ feat) {
    int i = blockIdx.x * 256 + threadIdx.x;
    if (i >= BN) return;
    int b = i / N, n = i % N;
    float* x = g_x + (size_t)i * IN_DIM;
    x[0] = pm25[(size_t)(b * HIST + (HIST - 1)) * N + n];
    const float* f = feat + ((size_t)(b * TSTEPS + HIST) * N + n) * 8;
#pragma unroll
    for (int k = 0; k < 8; k++) x[1 + k] = f[k];
#pragma unroll
    for (int j = 0; j < HID; j++) g_hn[j * BN + i] = 0.0f;
#pragma unroll
    for (int k = 0; k < GNN_OUT; k++) g_agg[(size_t)i * GNN_OUT + k] = 0.0f;
}

// ---------------------------------------------------------------------------
// Edge kernel: one thread per (batch, edge).
// Computes edge MLP (21->32->30, sigmoid), folds in the node projection
// (30->13) so only 13 values get scattered (+tgt / -src) per edge.
// ---------------------------------------------------------------------------
__global__ void __launch_bounds__(256) k_edge(
    const float* __restrict__ ea, const void* __restrict__ ei,
    const float* __restrict__ wm, const float* __restrict__ ws,
    const float* __restrict__ ew1, const float* __restrict__ eb1,
    const float* __restrict__ ew2, const float* __restrict__ eb2,
    const float* __restrict__ nw)
{
    __shared__ float s_w1[21 * 32];
    __shared__ float s_b1[32];
    __shared__ float s_w2[32 * 30];
    __shared__ float s_b2[30];
    __shared__ float s_nw[30 * 13];
    for (int i = threadIdx.x; i < 21 * 32; i += 256) s_w1[i] = ew1[i];
    for (int i = threadIdx.x; i < 32; i += 256) s_b1[i] = eb1[i];
    for (int i = threadIdx.x; i < 32 * 30; i += 256) s_w2[i] = ew2[i];
    for (int i = threadIdx.x; i < 30; i += 256) s_b2[i] = eb2[i];
    for (int i = threadIdx.x; i < 30 * 13; i += 256) s_nw[i] = nw[i];
    __syncthreads();

    int idx = blockIdx.x * 256 + threadIdx.x;
    if (idx >= B * E) return;
    int e = idx % E;
    int b = idx / E;

    int src, tgt;
    if (g_is64) {
        const long long* p = (const long long*)ei;
        src = (int)p[e]; tgt = (int)p[E + e];
    } else {
        const int* p = (const int*)ei;
        src = p[e]; tgt = p[E + e];
    }

    const float* xs = g_x + (size_t)(b * N + src) * IN_DIM;
    const float* xt = g_x + (size_t)(b * N + tgt) * IN_DIM;
    float in[21];
#pragma unroll
    for (int k = 0; k < 9; k++) in[k] = xs[k];
#pragma unroll
    for (int k = 0; k < 9; k++) in[9 + k] = xt[k];

    float a0 = ea[2 * e], a1 = ea[2 * e + 1];
    in[18] = (a0 - g_stats[4]) * g_stats[6];
    in[19] = (a1 - g_stats[5]) * g_stats[7];
    float dist = fmaxf(a0, 1e-3f);
    float wsd0 = fmaxf(ws[0], 1e-6f);
    float wsd1 = fmaxf(ws[1], 1e-6f);
    float wind0 = in[7] * wsd0 + wm[0];   // src last-2 features are x[7], x[8]
    float wind1 = in[8] * wsd1 + wm[1];
    float speed = fmaxf(wind0, 0.0f);
    float wdir = wind1 * 0.017453292519943295f;  // deg2rad
    float theta = fabsf(a1 - wdir);
    in[20] = fmaxf(0.0f, 3.0f * speed * cosf(theta) / dist);

    float h1[32];
#pragma unroll
    for (int j = 0; j < 32; j++) {
        float acc = s_b1[j];
#pragma unroll
        for (int i = 0; i < 21; i++) acc += in[i] * s_w1[i * 32 + j];
        h1[j] = sigmoidf_(acc);
    }
    float h2[30];
#pragma unroll
    for (int j = 0; j < 30; j++) {
        float acc = s_b2[j];
#pragma unroll
        for (int i = 0; i < 32; i++) acc += h1[i] * s_w2[i * 30 + j];
        h2[j] = sigmoidf_(acc);
    }

    float* at = g_agg + (size_t)(b * N + tgt) * GNN_OUT;
    float* as = g_agg + (size_t)(b * N + src) * GNN_OUT;
#pragma unroll
    for (int k = 0; k < GNN_OUT; k++) {
        float v = 0.0f;
#pragma unroll
        for (int j = 0; j < 30; j++) v += h2[j] * s_nw[j * 13 + k];
        atomicAdd(at + k, v);
        atomicAdd(as + k, -v);
    }
}

// ---------------------------------------------------------------------------
// Node kernel: x_gnn = sigmoid(agg + n_b); xc = [x_gnn, x]; GRU; fc;
// writes output for step t, zeroes agg, and builds x for step t+1.
// Weights staged in 68KB dynamic shared.
// ---------------------------------------------------------------------------
__global__ void __launch_bounds__(128) k_node(
    const float* __restrict__ feat,
    const float* __restrict__ gwi, const float* __restrict__ gwh,
    const float* __restrict__ gbi, const float* __restrict__ gbh,
    const float* __restrict__ nb, const float* __restrict__ fcw,
    const float* __restrict__ fcb, float* __restrict__ out, int t)
{
    extern __shared__ float sm[];
    float* s_wi = sm;                 // 192*22 = 4224
    float* s_wh = sm + 4224;          // 192*64 = 12288 (16B aligned)
    float* s_bi = s_wh + 12288;       // 192
    float* s_bh = s_bi + 192;         // 192
    float* s_nb = s_bh + 192;         // 13
    float* s_fw = s_nb + 13;          // 64
    for (int i = threadIdx.x; i < 4224; i += 128) s_wi[i] = gwi[i];
    for (int i = threadIdx.x; i < 12288; i += 128) s_wh[i] = gwh[i];
    for (int i = threadIdx.x; i < 192; i += 128) { s_bi[i] = gbi[i]; s_bh[i] = gbh[i]; }
    for (int i = threadIdx.x; i < 64; i += 128) s_fw[i] = fcw[i];
    if (threadIdx.x < 13) s_nb[threadIdx.x] = nb[threadIdx.x];
    __syncthreads();

    int i = blockIdx.x * 128 + threadIdx.x;
    if (i >= BN) return;
    int b = i / N, n = i % N;

    float xc[22];
    float* agg = g_agg + (size_t)i * GNN_OUT;
#pragma unroll
    for (int k = 0; k < 13; k++) {
        xc[k] = sigmoidf_(agg[k] + s_nb[k]);
        agg[k] = 0.0f;  // zero for next step's scatter
    }
    const float* xrow = g_x + (size_t)i * IN_DIM;
#pragma unroll
    for (int k = 0; k < 9; k++) xc[13 + k] = xrow[k];

    float h[64];
#pragma unroll
    for (int j = 0; j < 64; j++) h[j] = g_hn[j * BN + i];

    float xn = fcb[0];
    for (int k = 0; k < 64; k++) {
        float ir = s_bi[k], iz = s_bi[64 + k], inn = s_bi[128 + k];
        const float* wr = s_wi + k * 22;
        const float* wz = s_wi + (64 + k) * 22;
        const float* wn = s_wi + (128 + k) * 22;
#pragma unroll
        for (int q = 0; q < 22; q++) {
            float xq = xc[q];
            ir += xq * wr[q]; iz += xq * wz[q]; inn += xq * wn[q];
        }
        float hr = s_bh[k], hz = s_bh[64 + k], hnn = s_bh[128 + k];
        const float4* vr = (const float4*)(s_wh + k * 64);
        const float4* vz = (const float4*)(s_wh + (64 + k) * 64);
        const float4* vn = (const float4*)(s_wh + (128 + k) * 64);
#pragma unroll
        for (int q = 0; q < 16; q++) {
            float4 a = vr[q], c = vz[q], d = vn[q];
            hr  += h[4 * q] * a.x + h[4 * q + 1] * a.y + h[4 * q + 2] * a.z + h[4 * q + 3] * a.w;
            hz  += h[4 * q] * c.x + h[4 * q + 1] * c.y + h[4 * q + 2] * c.z + h[4 * q + 3] * c.w;
            hnn += h[4 * q] * d.x + h[4 * q + 1] * d.y + h[4 * q + 2] * d.z + h[4 * q + 3] * d.w;
        }
        float r = sigmoidf_(ir + hr);
        float z = sigmoidf_(iz + hz);
        float ng = tanhf(inn + r * hnn);
        float h_old = g_hn[k * BN + i];       // read-before-write, same thread
        float hk = (1.0f - z) * ng + z * h_old;
        g_hn[k * BN + i] = hk;
        xn += hk * s_fw[k];
    }

    out[(size_t)(b * N + n) * PRED + t] = xn;

    if (t + 1 < PRED) {
        float* xw = g_x + (size_t)i * IN_DIM;
        xw[0] = xn;
        const float* f = feat + ((size_t)(b * TSTEPS + HIST + t + 1) * N + n) * 8;
#pragma unroll
        for (int k = 0; k < 8; k++) xw[1 + k] = f[k];
    }
}

// ---------------------------------------------------------------------------
extern "C" void kernel_launch(void* const* d_in, const int* in_sizes, int n_in,
                              void* d_out, int out_size) {
    const float* pm25 = (const float*)d_in[0];
    const float* feat = (const float*)d_in[1];
    const float* ea   = (const float*)d_in[2];
    const float* wm   = (const float*)d_in[3];
    const float* ws   = (const float*)d_in[4];
    const float* ew1  = (const float*)d_in[5];
    const float* eb1  = (const float*)d_in[6];
    const float* ew2  = (const float*)d_in[7];
    const float* eb2  = (const float*)d_in[8];
    const float* nw   = (const float*)d_in[9];
    const float* nb   = (const float*)d_in[10];
    const float* gwi  = (const float*)d_in[11];
    const float* gwh  = (const float*)d_in[12];
    const float* gbi  = (const float*)d_in[13];
    const float* gbh  = (const float*)d_in[14];
    const float* fcw  = (const float*)d_in[15];
    const float* fcb  = (const float*)d_in[16];
    const void*  ei   = d_in[17];
    float* out = (float*)d_out;

    constexpr int NODE_SMEM = (4224 + 12288 + 192 + 192 + 13 + 64) * 4; // 67892 B
    cudaFuncSetAttribute(k_node, cudaFuncAttributeMaxDynamicSharedMemorySize,
                         NODE_SMEM);

    k_detect<<<1, 256>>>((const unsigned int*)ei);
    k_stats<<<232, 256>>>(ea);
    k_finalize<<<1, 1>>>();
    k_init<<<(BN + 255) / 256, 256>>>(pm25, feat);

    for (int t = 0; t < PRED; t++) {
        k_edge<<<(B * E + 255) / 256, 256>>>(ea, ei, wm, ws, ew1, eb1, ew2,
                                             eb2, nw);
        k_node<<<(BN + 127) / 128, 128, NODE_SMEM>>>(feat, gwi, gwh, gbi, gbh,
                                                     nb, fcw, fcb, out, t);
    }
}

// round 17
// speedup vs baseline: 1.0052x; 1.0003x over previous
#include <cuda_runtime.h>
#include <math.h>

namespace {
constexpr int B = 4;
constexpr int N = 10000;
constexpr int E = 160000;
constexpr int HIST = 8;
constexpr int PRED = 12;
constexpr int HID = 64;
constexpr int GNN_OUT = 13;
constexpr int IN_DIM = 9;
constexpr int BN = B * N;
constexpr int TSTEPS = HIST + PRED; // 20
}

// Persistent scratch (device globals — no allocation allowed)
__device__ float g_x[BN * IN_DIM];        // node features [B*N][9]
__device__ float g_hn[HID * BN];          // GRU state, transposed [64][B*N] for coalescing
__device__ float g_agg[BN * GNN_OUT];     // scatter target [B*N][13]
__device__ float g_stats[8];              // sum0,sum1,sq0,sq1, mean0,mean1,istd0,istd1
__device__ int   g_is64;                  // edge_index dtype flag

__device__ __forceinline__ float sigmoidf_(float x) {
    return 1.0f / (1.0f + __expf(-x));
}

// ---------------------------------------------------------------------------
// Detect int64 vs int32 edge_index (values < 10000 => high 32-bit words all 0
// iff int64), and zero the stats accumulators.
// ---------------------------------------------------------------------------
__global__ void k_detect(const unsigned int* __restrict__ ei_raw) {
    __shared__ int s_ok;
    if (threadIdx.x == 0) s_ok = 1;
    __syncthreads();
    if (ei_raw[2 * threadIdx.x + 1] != 0u) s_ok = 0;  // benign same-value race
    __syncthreads();
    if (threadIdx.x < 4) g_stats[threadIdx.x] = 0.0f;
    if (threadIdx.x == 0) g_is64 = s_ok;
}

// ---------------------------------------------------------------------------
// edge_attr mean / sample-std (ddof=1) over E rows, 2 cols
// ---------------------------------------------------------------------------
__global__ void k_stats(const float* __restrict__ ea) {
    float s0 = 0.f, s1 = 0.f, q0 = 0.f, q1 = 0.f;
    for (int e = blockIdx.x * blockDim.x + threadIdx.x; e < E;
         e += gridDim.x * blockDim.x) {
        float a0 = ea[2 * e], a1 = ea[2 * e + 1];
        s0 += a0; s1 += a1; q0 += a0 * a0; q1 += a1 * a1;
    }
#pragma unroll
    for (int o = 16; o > 0; o >>= 1) {
        s0 += __shfl_down_sync(0xffffffffu, s0, o);
        s1 += __shfl_down_sync(0xffffffffu, s1, o);
        q0 += __shfl_down_sync(0xffffffffu, q0, o);
        q1 += __shfl_down_sync(0xffffffffu, q1, o);
    }
    __shared__ float sh[4][8];
    int w = threadIdx.x >> 5, l = threadIdx.x & 31;
    if (l == 0) { sh[0][w] = s0; sh[1][w] = s1; sh[2][w] = q0; sh[3][w] = q1; }
    __syncthreads();
    if (threadIdx.x == 0) {
        float t0 = 0.f, t1 = 0.f, t2 = 0.f, t3 = 0.f;
        int nwp = blockDim.x >> 5;
        for (int k = 0; k < nwp; k++) {
            t0 += sh[0][k]; t1 += sh[1][k]; t2 += sh[2][k]; t3 += sh[3][k];
        }
        atomicAdd(&g_stats[0], t0); atomicAdd(&g_stats[1], t1);
        atomicAdd(&g_stats[2], t2); atomicAdd(&g_stats[3], t3);
    }
}

__global__ void k_finalize() {
    float inv = 1.0f / (float)E;
    float m0 = g_stats[0] * inv, m1 = g_stats[1] * inv;
    float v0 = (g_stats[2] - g_stats[0] * m0) / (float)(E - 1);
    float v1 = (g_stats[3] - g_stats[1] * m1) / (float)(E - 1);
    float sd0 = fmaxf(sqrtf(fmaxf(v0, 0.f)), 1e-6f);
    float sd1 = fmaxf(sqrtf(fmaxf(v1, 0.f)), 1e-6f);
    g_stats[4] = m0; g_stats[5] = m1;
    g_stats[6] = 1.0f / sd0; g_stats[7] = 1.0f / sd1;
}

// ---------------------------------------------------------------------------
// Init: x0 = [pm25_hist[:, -1], feature[:, HIST]]; hn = 0; agg = 0
// ---------------------------------------------------------------------------
__global__ void k_init(const float* __restrict__ pm25,
                       const float* __restrict__ feat) {
    int i = blockIdx.x * 256 + threadIdx.x;
    if (i >= BN) return;
    int b = i / N, n = i % N;
    float* x = g_x + (size_t)i * IN_DIM;
    x[0] = pm25[(size_t)(b * HIST + (HIST - 1)) * N + n];
    const float* f = feat + ((size_t)(b * TSTEPS + HIST) * N + n) * 8;
#pragma unroll
    for (int k = 0; k < 8; k++) x[1 + k] = f[k];
#pragma unroll
    for (int j = 0; j < HID; j++) g_hn[j * BN + i] = 0.0f;
#pragma unroll
    for (int k = 0; k < GNN_OUT; k++) g_agg[(size_t)i * GNN_OUT + k] = 0.0f;
}

// ---------------------------------------------------------------------------
// Edge kernel: one thread per (batch, edge).
// Computes edge MLP (21->32->30, sigmoid), folds in the node projection
// (30->13) so only 13 values get scattered (+tgt / -src) per edge.
// ---------------------------------------------------------------------------
__global__ void __launch_bounds__(256) k_edge(
    const float* __restrict__ ea, const void* __restrict__ ei,
    const float* __restrict__ wm, const float* __restrict__ ws,
    const float* __restrict__ ew1, const float* __restrict__ eb1,
    const float* __restrict__ ew2, const float* __restrict__ eb2,
    const float* __restrict__ nw)
{
    __shared__ float s_w1[21 * 32];
    __shared__ float s_b1[32];
    __shared__ float s_w2[32 * 30];
    __shared__ float s_b2[30];
    __shared__ float s_nw[30 * 13];
    for (int i = threadIdx.x; i < 21 * 32; i += 256) s_w1[i] = ew1[i];
    for (int i = threadIdx.x; i < 32; i += 256) s_b1[i] = eb1[i];
    for (int i = threadIdx.x; i < 32 * 30; i += 256) s_w2[i] = ew2[i];
    for (int i = threadIdx.x; i < 30; i += 256) s_b2[i] = eb2[i];
    for (int i = threadIdx.x; i < 30 * 13; i += 256) s_nw[i] = nw[i];
    __syncthreads();

    int idx = blockIdx.x * 256 + threadIdx.x;
    if (idx >= B * E) return;
    int e = idx % E;
    int b = idx / E;

    int src, tgt;
    if (g_is64) {
        const long long* p = (const long long*)ei;
        src = (int)p[e]; tgt = (int)p[E + e];
    } else {
        const int* p = (const int*)ei;
        src = p[e]; tgt = p[E + e];
    }

    const float* xs = g_x + (size_t)(b * N + src) * IN_DIM;
    const float* xt = g_x + (size_t)(b * N + tgt) * IN_DIM;
    float in[21];
#pragma unroll
    for (int k = 0; k < 9; k++) in[k] = xs[k];
#pragma unroll
    for (int k = 0; k < 9; k++) in[9 + k] = xt[k];

    float a0 = ea[2 * e], a1 = ea[2 * e + 1];
    in[18] = (a0 - g_stats[4]) * g_stats[6];
    in[19] = (a1 - g_stats[5]) * g_stats[7];
    float dist = fmaxf(a0, 1e-3f);
    float wsd0 = fmaxf(ws[0], 1e-6f);
    float wsd1 = fmaxf(ws[1], 1e-6f);
    float wind0 = in[7] * wsd0 + wm[0];   // src last-2 features are x[7], x[8]
    float wind1 = in[8] * wsd1 + wm[1];
    float speed = fmaxf(wind0, 0.0f);
    float wdir = wind1 * 0.017453292519943295f;  // deg2rad
    float theta = fabsf(a1 - wdir);
    in[20] = fmaxf(0.0f, 3.0f * speed * cosf(theta) / dist);

    float h1[32];
#pragma unroll
    for (int j = 0; j < 32; j++) {
        float acc = s_b1[j];
#pragma unroll
        for (int i = 0; i < 21; i++) acc += in[i] * s_w1[i * 32 + j];
        h1[j] = sigmoidf_(acc);
    }
    float h2[30];
#pragma unroll
    for (int j = 0; j < 30; j++) {
        float acc = s_b2[j];
#pragma unroll
        for (int i = 0; i < 32; i++) acc += h1[i] * s_w2[i * 30 + j];
        h2[j] = sigmoidf_(acc);
    }

    float* at = g_agg + (size_t)(b * N + tgt) * GNN_OUT;
    float* as = g_agg + (size_t)(b * N + src) * GNN_OUT;
#pragma unroll
    for (int k = 0; k < GNN_OUT; k++) {
        float v = 0.0f;
#pragma unroll
        for (int j = 0; j < 30; j++) v += h2[j] * s_nw[j * 13 + k];
        atomicAdd(at + k, v);
        atomicAdd(as + k, -v);
    }
}

// ---------------------------------------------------------------------------
// Node kernel: x_gnn = sigmoid(agg + n_b); xc = [x_gnn, x]; GRU; fc;
// writes output for step t, zeroes agg, and builds x for step t+1.
// Weights staged in 68KB dynamic shared.
// ---------------------------------------------------------------------------
__global__ void __launch_bounds__(128) k_node(
    const float* __restrict__ feat,
    const float* __restrict__ gwi, const float* __restrict__ gwh,
    const float* __restrict__ gbi, const float* __restrict__ gbh,
    const float* __restrict__ nb, const float* __restrict__ fcw,
    const float* __restrict__ fcb, float* __restrict__ out, int t)
{
    extern __shared__ float sm[];
    float* s_wi = sm;                 // 192*22 = 4224
    float* s_wh = sm + 4224;          // 192*64 = 12288 (16B aligned)
    float* s_bi = s_wh + 12288;       // 192
    float* s_bh = s_bi + 192;         // 192
    float* s_nb = s_bh + 192;         // 13
    float* s_fw = s_nb + 13;          // 64
    for (int i = threadIdx.x; i < 4224; i += 128) s_wi[i] = gwi[i];
    for (int i = threadIdx.x; i < 12288; i += 128) s_wh[i] = gwh[i];
    for (int i = threadIdx.x; i < 192; i += 128) { s_bi[i] = gbi[i]; s_bh[i] = gbh[i]; }
    for (int i = threadIdx.x; i < 64; i += 128) s_fw[i] = fcw[i];
    if (threadIdx.x < 13) s_nb[threadIdx.x] = nb[threadIdx.x];
    __syncthreads();

    int i = blockIdx.x * 128 + threadIdx.x;
    if (i >= BN) return;
    int b = i / N, n = i % N;

    float xc[22];
    float* agg = g_agg + (size_t)i * GNN_OUT;
#pragma unroll
    for (int k = 0; k < 13; k++) {
        xc[k] = sigmoidf_(agg[k] + s_nb[k]);
        agg[k] = 0.0f;  // zero for next step's scatter
    }
    const float* xrow = g_x + (size_t)i * IN_DIM;
#pragma unroll
    for (int k = 0; k < 9; k++) xc[13 + k] = xrow[k];

    float h[64];
#pragma unroll
    for (int j = 0; j < 64; j++) h[j] = g_hn[j * BN + i];

    float xn = fcb[0];
    for (int k = 0; k < 64; k++) {
        float ir = s_bi[k], iz = s_bi[64 + k], inn = s_bi[128 + k];
        const float* wr = s_wi + k * 22;
        const float* wz = s_wi + (64 + k) * 22;
        const float* wn = s_wi + (128 + k) * 22;
#pragma unroll
        for (int q = 0; q < 22; q++) {
            float xq = xc[q];
            ir += xq * wr[q]; iz += xq * wz[q]; inn += xq * wn[q];
        }
        float hr = s_bh[k], hz = s_bh[64 + k], hnn = s_bh[128 + k];
        const float4* vr = (const float4*)(s_wh + k * 64);
        const float4* vz = (const float4*)(s_wh + (64 + k) * 64);
        const float4* vn = (const float4*)(s_wh + (128 + k) * 64);
#pragma unroll
        for (int q = 0; q < 16; q++) {
            float4 a = vr[q], c = vz[q], d = vn[q];
            hr  += h[4 * q] * a.x + h[4 * q + 1] * a.y + h[4 * q + 2] * a.z + h[4 * q + 3] * a.w;
            hz  += h[4 * q] * c.x + h[4 * q + 1] * c.y + h[4 * q + 2] * c.z + h[4 * q + 3] * c.w;
            hnn += h[4 * q] * d.x + h[4 * q + 1] * d.y + h[4 * q + 2] * d.z + h[4 * q + 3] * d.w;
        }
        float r = sigmoidf_(ir + hr);
        float z = sigmoidf_(iz + hz);
        float ng = tanhf(inn + r * hnn);
        float h_old = g_hn[k * BN + i];       // read-before-write, same thread
        float hk = (1.0f - z) * ng + z * h_old;
        g_hn[k * BN + i] = hk;
        xn += hk * s_fw[k];
    }

    out[(size_t)(b * N + n) * PRED + t] = xn;

    if (t + 1 < PRED) {
        float* xw = g_x + (size_t)i * IN_DIM;
        xw[0] = xn;
        const float* f = feat + ((size_t)(b * TSTEPS + HIST + t + 1) * N + n) * 8;
#pragma unroll
        for (int k = 0; k < 8; k++) xw[1 + k] = f[k];
    }
}

// ---------------------------------------------------------------------------
extern "C" void kernel_launch(void* const* d_in, const int* in_sizes, int n_in,
                              void* d_out, int out_size) {
    const float* pm25 = (const float*)d_in[0];
    const float* feat = (const float*)d_in[1];
    const float* ea   = (const float*)d_in[2];
    const float* wm   = (const float*)d_in[3];
    const float* ws   = (const float*)d_in[4];
    const float* ew1  = (const float*)d_in[5];
    const float* eb1  = (const float*)d_in[6];
    const float* ew2  = (const float*)d_in[7];
    const float* eb2  = (const float*)d_in[8];
    const float* nw   = (const float*)d_in[9];
    const float* nb   = (const float*)d_in[10];
    const float* gwi  = (const float*)d_in[11];
    const float* gwh  = (const float*)d_in[12];
    const float* gbi  = (const float*)d_in[13];
    const float* gbh  = (const float*)d_in[14];
    const float* fcw  = (const float*)d_in[15];
    const float* fcb  = (const float*)d_in[16];
    const void*  ei   = d_in[17];
    float* out = (float*)d_out;

    constexpr int NODE_SMEM = (4224 + 12288 + 192 + 192 + 13 + 64) * 4; // 67892 B
    cudaFuncSetAttribute(k_node, cudaFuncAttributeMaxDynamicSharedMemorySize,
                         NODE_SMEM);

    k_detect<<<1, 256>>>((const unsigned int*)ei);
    k_stats<<<232, 256>>>(ea);
    k_finalize<<<1, 1>>>();
    k_init<<<(BN + 255) / 256, 256>>>(pm25, feat);

    for (int t = 0; t < PRED; t++) {
        k_edge<<<(B * E + 255) / 256, 256>>>(ea, ei, wm, ws, ew1, eb1, ew2,
                                             eb2, nw);
        k_node<<<(BN + 127) / 128, 128, NODE_SMEM>>>(feat, gwi, gwh, gbi, gbh,
                                                     nb, fcw, fcb, out, t);
    }
}